// round 3
// baseline (speedup 1.0000x reference)
#include <cuda_runtime.h>
#include <cuda_bf16.h>

#define N_NODES   50000
#define N_EDGES   500000
#define MASK_WORDS 2000000
#define GRID_MAIN 3907

// smem layout (float indices)
#define XS_OFF   0            // [128 c][132]  X^T (c-major, m contiguous); pass b: edge feats
#define HC_OFF   16896        // [64 h][132]   relu(layer1) chunk
#define W1T_OFF  25344        // [128 k][68]   W1 chunk transposed
#define W2T_OFF  34048        // [64 h][132]   W2 chunk transposed
#define IDX_OFF  42496        // src[128], dst[128]
#define SS_OFF   16896        // final S [128 m][132] (reuses HC/W1T after last GEMM2)
#define SMEM_FLOATS 42752
#define SMEM_BYTES  (SMEM_FLOATS * 4)

__device__ unsigned g_mask[MASK_WORDS];
__device__ float    g_cvec[128];
__device__ int      g_is64;

typedef unsigned long long ull;

__device__ __forceinline__ void fma2(ull &d, ull a, ull b) {
    asm("fma.rn.f32x2 %0, %1, %2, %0;" : "+l"(d) : "l"(a), "l"(b));
}
__device__ __forceinline__ void add2(ull &d, ull a) {
    asm("add.rn.f32x2 %0, %0, %1;" : "+l"(d) : "l"(a));
}
__device__ __forceinline__ ull dup2(float v) {
    ull r; asm("mov.b64 %0, {%1, %1};" : "=l"(r) : "f"(v)); return r;
}
__device__ __forceinline__ float2 unpk(ull v) {
    float2 r; asm("mov.b64 {%0, %1}, %2;" : "=f"(r.x), "=f"(r.y) : "l"(v)); return r;
}

// ---------------- JAX threefry2x32, key (0, 42) ----------------
__device__ __forceinline__ unsigned rotl32(unsigned x, int d) {
    return __funnelshift_l(x, x, d);
}
__device__ __forceinline__ void threefry(unsigned c0, unsigned c1,
                                         unsigned &o0, unsigned &o1) {
    const unsigned k0 = 0u, k1 = 42u, k2 = 0x1BD11BDAu ^ 42u;
    unsigned x0 = c0 + k0, x1 = c1 + k1;
#define TF4(ra, rb, rc, rd)                                  \
    x0 += x1; x1 = rotl32(x1, ra); x1 ^= x0;                 \
    x0 += x1; x1 = rotl32(x1, rb); x1 ^= x0;                 \
    x0 += x1; x1 = rotl32(x1, rc); x1 ^= x0;                 \
    x0 += x1; x1 = rotl32(x1, rd); x1 ^= x0;
    TF4(13, 15, 26, 6)  x0 += k1; x1 += k2 + 1u;
    TF4(17, 29, 16, 24) x0 += k2; x1 += k0 + 2u;
    TF4(13, 15, 26, 6)  x0 += k0; x1 += k1 + 3u;
    TF4(17, 29, 16, 24) x0 += k1; x1 += k2 + 4u;
    TF4(13, 15, 26, 6)  x0 += k2; x1 += k0 + 5u;
#undef TF4
    o0 = x0; o1 = x1;
}

// JAX partitionable threefry (default since 0.5.0):
//   bits[j] = o0 ^ o1 with counters (hi32(j)=0, lo32(j)=j)
// keep = ((bits >> 9) < 7549747)   (7549747 == 0.9f * 2^23, strict <)
__global__ void ef_mask_kernel() {
    int t = blockIdx.x * blockDim.x + threadIdx.x;
    if (t >= MASK_WORDS) return;
    unsigned base = (unsigned)t * 32u;
    unsigned w = 0u;
#pragma unroll 4
    for (int k = 0; k < 32; k++) {
        unsigned o0, o1;
        threefry(0u, base + k, o0, o1);
        w |= ((unsigned)(((o0 ^ o1) >> 9) < 7549747u)) << k;
    }
    g_mask[t] = w;
}

// int64 edge_index => all odd 32-bit words are zero (ids < 50000)
__global__ void ef_detect_kernel(const unsigned* __restrict__ ei) {
    unsigned v = ei[2 * threadIdx.x + 1];
    unsigned b = __ballot_sync(0xffffffffu, v == 0u);
    if (threadIdx.x == 0) g_is64 = (b == 0xffffffffu) ? 1 : 0;
}

// g_cvec[n] = fcnn_c(global)[n] + b2a[n] + b2b[n]
__global__ void ef_hglob_kernel(const float* __restrict__ gf,
                                const float* __restrict__ W1c, const float* __restrict__ b1c,
                                const float* __restrict__ W2c, const float* __restrict__ b2c,
                                const float* __restrict__ b2a, const float* __restrict__ b2b) {
    __shared__ float sg[128];
    __shared__ float hid[256];
    int t = threadIdx.x;
    if (t < 128) sg[t] = gf[t];
    __syncthreads();
    float acc = b1c[t];
#pragma unroll 8
    for (int k = 0; k < 128; k++) acc += sg[k] * W1c[t * 128 + k];
    hid[t] = fmaxf(acc, 0.f);
    __syncthreads();
    if (t < 128) {
        float a2 = b2c[t];
#pragma unroll 8
        for (int k = 0; k < 256; k++) a2 += hid[k] * W2c[t * 256 + k];
        g_cvec[t] = a2 + b2a[t] + b2b[t];
    }
}

// ---------------- main fused kernel: one CTA = 128 edges ----------------
__global__ __launch_bounds__(256, 1)
void ef_main_kernel(const float* __restrict__ nf,
                    const void*  __restrict__ eidx,
                    const float* __restrict__ ef,
                    const float* __restrict__ W1a, const float* __restrict__ b1a,
                    const float* __restrict__ W2a,
                    const float* __restrict__ W1b, const float* __restrict__ b1b,
                    const float* __restrict__ W2b,
                    float* __restrict__ out) {
    extern __shared__ float sm[];
    float* XS  = sm + XS_OFF;
    float* HC  = sm + HC_OFF;
    float* W1T = sm + W1T_OFF;
    float* W2T = sm + W2T_OFF;
    float* SS  = sm + SS_OFF;
    int*   sidx = (int*)(sm + IDX_OFF);

    const int tid = threadIdx.x;
    const int tx  = tid & 15;
    const int ty  = tid >> 4;
    const int m0  = ty * 8;
    const int e0  = blockIdx.x * 128;

    // indices
    if (tid < 128) {
        int ec = min(e0 + tid, N_EDGES - 1);
        int s, d;
        if (g_is64) {
            const long long* p = (const long long*)eidx;
            s = (int)p[ec]; d = (int)p[N_EDGES + ec];
        } else {
            const int* p = (const int*)eidx;
            s = p[ec]; d = p[N_EDGES + ec];
        }
        sidx[tid] = s; sidx[128 + tid] = d;
    }
    __syncthreads();

    // gather node sum into XS[c][m] (two threads per edge row)
    {
        int m = tid & 127;
        int ch = (tid >> 7) * 64;
        const float* ps = nf + (size_t)sidx[m] * 128;
        const float* pd = nf + (size_t)sidx[128 + m] * 128;
#pragma unroll 4
        for (int c4 = 0; c4 < 16; c4++) {
            int c = ch + c4 * 4;
            float4 va = *(const float4*)(ps + c);
            float4 vb = *(const float4*)(pd + c);
            XS[(c + 0) * 132 + m] = va.x + vb.x;
            XS[(c + 1) * 132 + m] = va.y + vb.y;
            XS[(c + 2) * 132 + m] = va.z + vb.z;
            XS[(c + 3) * 132 + m] = va.w + vb.w;
        }
    }

    ull sacc[4][8];
#pragma unroll
    for (int i = 0; i < 4; i++)
#pragma unroll
        for (int j = 0; j < 8; j++) sacc[i][j] = 0ull;

    for (int pass = 0; pass < 2; pass++) {
        const float* W1 = pass ? W1b : W1a;
        const float* B1 = pass ? b1b : b1a;
        const float* W2 = pass ? W2b : W2a;

        if (pass) {
            __syncthreads();  // pass-a GEMMs done with XS
            int m = tid & 127;
            int ch = (tid >> 7) * 64;
            int ec = min(e0 + m, N_EDGES - 1);
            const float* pe = ef + (size_t)ec * 128;
#pragma unroll 4
            for (int c4 = 0; c4 < 16; c4++) {
                int c = ch + c4 * 4;
                float4 v = *(const float4*)(pe + c);
                XS[(c + 0) * 132 + m] = v.x;
                XS[(c + 1) * 132 + m] = v.y;
                XS[(c + 2) * 132 + m] = v.z;
                XS[(c + 3) * 132 + m] = v.w;
            }
        }

        for (int hb = 0; hb < 256; hb += 64) {
            __syncthreads();  // previous chunk / gather complete

            // stage W1T[k][h] = W1[hb+h][k]
#pragma unroll
            for (int q = 0; q < 8; q++) {
                int f = tid + q * 256;            // 2048 float4s
                int h = f >> 5, k4 = (f & 31) << 2;
                float4 w = *(const float4*)(W1 + (size_t)(hb + h) * 128 + k4);
                W1T[(k4 + 0) * 68 + h] = w.x;
                W1T[(k4 + 1) * 68 + h] = w.y;
                W1T[(k4 + 2) * 68 + h] = w.z;
                W1T[(k4 + 3) * 68 + h] = w.w;
            }
            // stage W2T[h][n] = W2[n][hb+h]
#pragma unroll
            for (int q = 0; q < 8; q++) {
                int f = tid + q * 256;
                int n = f >> 4, kb = (f & 15) << 2;
                float4 w = *(const float4*)(W2 + (size_t)n * 256 + hb + kb);
                W2T[(kb + 0) * 132 + n] = w.x;
                W2T[(kb + 1) * 132 + n] = w.y;
                W2T[(kb + 2) * 132 + n] = w.z;
                W2T[(kb + 3) * 132 + n] = w.w;
            }
            __syncthreads();

            // GEMM1: acc1[m-pair][h] over k=128, h = tx + 16*j (64 wide)
            ull acc1[4][4];
#pragma unroll
            for (int i = 0; i < 4; i++)
#pragma unroll
                for (int j = 0; j < 4; j++) acc1[i][j] = 0ull;
#pragma unroll 4
            for (int k = 0; k < 128; k++) {
                ull a2[4];
#pragma unroll
                for (int i = 0; i < 4; i++)
                    a2[i] = *(const ull*)&XS[k * 132 + m0 + 2 * i];
#pragma unroll
                for (int j = 0; j < 4; j++) {
                    ull bd = dup2(W1T[k * 68 + tx + 16 * j]);
#pragma unroll
                    for (int i = 0; i < 4; i++) fma2(acc1[i][j], a2[i], bd);
                }
            }
            // bias + relu -> HC[h][m]
#pragma unroll
            for (int j = 0; j < 4; j++) {
                float bb = __ldg(B1 + hb + tx + 16 * j);
#pragma unroll
                for (int i = 0; i < 4; i++) {
                    float2 v = unpk(acc1[i][j]);
                    v.x = fmaxf(v.x + bb, 0.f);
                    v.y = fmaxf(v.y + bb, 0.f);
                    *(float2*)&HC[(tx + 16 * j) * 132 + m0 + 2 * i] = v;
                }
            }
            __syncthreads();

            // GEMM2: sacc += HC @ W2T over h=64, n = tx + 16*j (128 wide)
#pragma unroll 4
            for (int h = 0; h < 64; h++) {
                ull a2[4];
#pragma unroll
                for (int i = 0; i < 4; i++)
                    a2[i] = *(const ull*)&HC[h * 132 + m0 + 2 * i];
#pragma unroll
                for (int j = 0; j < 8; j++) {
                    ull bd = dup2(W2T[h * 132 + tx + 16 * j]);
#pragma unroll
                    for (int i = 0; i < 4; i++) fma2(sacc[i][j], a2[i], bd);
                }
            }
        }
    }
    __syncthreads();  // all GEMM2 reads of HC done (SS overlaps HC/W1T)

    // ---- epilogue: +cvec, instance norm, dropout, relu, residual ----
#pragma unroll
    for (int j = 0; j < 8; j++) {
        ull cd = dup2(g_cvec[tx + 16 * j]);
#pragma unroll
        for (int i = 0; i < 4; i++) add2(sacc[i][j], cd);
    }

#pragma unroll
    for (int i = 0; i < 4; i++) {
        ull s2 = 0ull, q2 = 0ull;
#pragma unroll
        for (int j = 0; j < 8; j++) {
            add2(s2, sacc[i][j]);
            fma2(q2, sacc[i][j], sacc[i][j]);
        }
        float2 s = unpk(s2), q = unpk(q2);
#pragma unroll
        for (int w = 1; w < 16; w <<= 1) {
            s.x += __shfl_xor_sync(0xffffffffu, s.x, w);
            s.y += __shfl_xor_sync(0xffffffffu, s.y, w);
            q.x += __shfl_xor_sync(0xffffffffu, q.x, w);
            q.y += __shfl_xor_sync(0xffffffffu, q.y, w);
        }
        float mlo = s.x * 0.0078125f, mhi = s.y * 0.0078125f;
        float rlo = rsqrtf(fmaxf(q.x * 0.0078125f - mlo * mlo, 0.f) + 1e-5f);
        float rhi = rsqrtf(fmaxf(q.y * 0.0078125f - mhi * mhi, 0.f) + 1e-5f);
        int mrow = m0 + 2 * i;
        int wlo = min(e0 + mrow,     N_EDGES - 1) * 4;
        int whi = min(e0 + mrow + 1, N_EDGES - 1) * 4;
#pragma unroll
        for (int j = 0; j < 8; j++) {
            int n = tx + 16 * j;
            float2 v = unpk(sacc[i][j]);
            float x = (v.x - mlo) * rlo;
            x = ((g_mask[wlo + (n >> 5)] >> (n & 31)) & 1u) ? (x / 0.9f) : 0.f;
            SS[mrow * 132 + n] = XS[n * 132 + mrow] + fmaxf(x, 0.f);
            float y = (v.y - mhi) * rhi;
            y = ((g_mask[whi + (n >> 5)] >> (n & 31)) & 1u) ? (y / 0.9f) : 0.f;
            SS[(mrow + 1) * 132 + n] = XS[n * 132 + mrow + 1] + fmaxf(y, 0.f);
        }
    }
    __syncthreads();

    // coalesced store
#pragma unroll
    for (int q = 0; q < 16; q++) {
        int f = tid + q * 256;                 // 4096 float4s
        int m = f >> 5, c4 = (f & 31) << 2;
        int e = e0 + m;
        if (e < N_EDGES)
            *(float4*)(out + (size_t)e * 128 + c4) = *(const float4*)&SS[m * 132 + c4];
    }
}

extern "C" void kernel_launch(void* const* d_in, const int* in_sizes, int n_in,
                              void* d_out, int out_size) {
    const float* nf  = (const float*)d_in[0];
    const void*  ei  = d_in[1];
    const float* ef  = (const float*)d_in[2];
    const float* gf  = (const float*)d_in[3];
    const float* W1a = (const float*)d_in[4];
    const float* b1a = (const float*)d_in[5];
    const float* W2a = (const float*)d_in[6];
    const float* b2a = (const float*)d_in[7];
    const float* W1b = (const float*)d_in[8];
    const float* b1b = (const float*)d_in[9];
    const float* W2b = (const float*)d_in[10];
    const float* b2b = (const float*)d_in[11];
    const float* W1c = (const float*)d_in[12];
    const float* b1c = (const float*)d_in[13];
    const float* W2c = (const float*)d_in[14];
    const float* b2c = (const float*)d_in[15];
    float* out = (float*)d_out;

    ef_mask_kernel<<<(MASK_WORDS + 255) / 256, 256>>>();
    ef_detect_kernel<<<1, 32>>>((const unsigned*)ei);
    ef_hglob_kernel<<<1, 256>>>(gf, W1c, b1c, W2c, b2c, b2a, b2b);

    cudaFuncSetAttribute(ef_main_kernel,
                         cudaFuncAttributeMaxDynamicSharedMemorySize, SMEM_BYTES);
    ef_main_kernel<<<GRID_MAIN, 256, SMEM_BYTES>>>(
        nf, ei, ef, W1a, b1a, W2a, W1b, b1b, W2b, out);
}

// round 6
// speedup vs baseline: 2.2395x; 2.2395x over previous
#include <cuda_runtime.h>
#include <cuda_bf16.h>
#include <cstdint>

#define N_NODES   50000
#define N_EDGES   500000
#define MASK_WORDS 2000000
#define GRID_MAIN 3907

// smem byte offsets
#define XH_OFF   0          // [128 m][128 k] bf16, row stride 272B
#define XL_OFF   34816
#define W1H_OFF  69632      // [64 n][128 k] bf16 chunk, stride 272B
#define W1L_OFF  87040
#define HH_OFF   104448     // [128 m][64 k] bf16, stride 144B
#define HL_OFF   122880
#define W2H_OFF  141312     // [128 n][64 k] bf16 chunk, stride 144B
#define W2L_OFF  159744
#define B1S_OFF  178176     // 256 floats
#define CV_OFF   179200     // 128 floats
#define S_OFF    69632      // fp32 [128][132]  (reuses W1/H/W2 area post-GEMM)
#define SMEM_BYTES 179712

__device__ unsigned g_mask[MASK_WORDS];
__device__ float    g_cvec[128];
__device__ int      g_is64;
__device__ __align__(16) __nv_bfloat16 g_wq[2][4][32768]; // [pass][W1h,W1l,W2h,W2l]

// ---------------- mma helpers ----------------
__device__ __forceinline__ void ldsm4(uint32_t* r, uint32_t addr) {
    asm volatile("ldmatrix.sync.aligned.m8n8.x4.shared.b16 {%0,%1,%2,%3}, [%4];"
        : "=r"(r[0]), "=r"(r[1]), "=r"(r[2]), "=r"(r[3]) : "r"(addr));
}
__device__ __forceinline__ void mma16816(float* d, const uint32_t* a,
                                         uint32_t b0, uint32_t b1) {
    asm volatile("mma.sync.aligned.m16n8k16.row.col.f32.bf16.bf16.f32 "
        "{%0,%1,%2,%3}, {%4,%5,%6,%7}, {%8,%9}, {%0,%1,%2,%3};"
        : "+f"(d[0]), "+f"(d[1]), "+f"(d[2]), "+f"(d[3])
        : "r"(a[0]), "r"(a[1]), "r"(a[2]), "r"(a[3]), "r"(b0), "r"(b1));
}
__device__ __forceinline__ uint32_t pack2(float v0, float v1) {
    return ((uint32_t)__bfloat16_as_ushort(__float2bfloat16(v1)) << 16) |
           (uint32_t)__bfloat16_as_ushort(__float2bfloat16(v0));
}

// ---------------- threefry (JAX partitionable, key (0,42)) ----------------
__device__ __forceinline__ unsigned rotl32(unsigned x, int d) {
    return __funnelshift_l(x, x, d);
}
__device__ __forceinline__ void threefry(unsigned c0, unsigned c1,
                                         unsigned &o0, unsigned &o1) {
    const unsigned k0 = 0u, k1 = 42u, k2 = 0x1BD11BDAu ^ 42u;
    unsigned x0 = c0 + k0, x1 = c1 + k1;
#define TF4(ra, rb, rc, rd)                                  \
    x0 += x1; x1 = rotl32(x1, ra); x1 ^= x0;                 \
    x0 += x1; x1 = rotl32(x1, rb); x1 ^= x0;                 \
    x0 += x1; x1 = rotl32(x1, rc); x1 ^= x0;                 \
    x0 += x1; x1 = rotl32(x1, rd); x1 ^= x0;
    TF4(13, 15, 26, 6)  x0 += k1; x1 += k2 + 1u;
    TF4(17, 29, 16, 24) x0 += k2; x1 += k0 + 2u;
    TF4(13, 15, 26, 6)  x0 += k0; x1 += k1 + 3u;
    TF4(17, 29, 16, 24) x0 += k1; x1 += k2 + 4u;
    TF4(13, 15, 26, 6)  x0 += k2; x1 += k0 + 5u;
#undef TF4
    o0 = x0; o1 = x1;
}

__global__ void ef_mask_kernel() {
    int t = blockIdx.x * blockDim.x + threadIdx.x;
    if (t >= MASK_WORDS) return;
    unsigned base = (unsigned)t * 32u;
    unsigned w = 0u;
#pragma unroll 4
    for (int k = 0; k < 32; k++) {
        unsigned o0, o1;
        threefry(0u, base + k, o0, o1);
        w |= ((unsigned)(((o0 ^ o1) >> 9) < 7549747u)) << k;
    }
    g_mask[t] = w;
}

__global__ void ef_detect_kernel(const unsigned* __restrict__ ei) {
    unsigned v = ei[2 * threadIdx.x + 1];
    unsigned b = __ballot_sync(0xffffffffu, v == 0u);
    if (threadIdx.x == 0) g_is64 = (b == 0xffffffffu) ? 1 : 0;
}

__global__ void ef_hglob_kernel(const float* __restrict__ gf,
                                const float* __restrict__ W1c, const float* __restrict__ b1c,
                                const float* __restrict__ W2c, const float* __restrict__ b2c,
                                const float* __restrict__ b2a, const float* __restrict__ b2b) {
    __shared__ float sg[128];
    __shared__ float hid[256];
    int t = threadIdx.x;
    if (t < 128) sg[t] = gf[t];
    __syncthreads();
    float acc = b1c[t];
#pragma unroll 8
    for (int k = 0; k < 128; k++) acc += sg[k] * W1c[t * 128 + k];
    hid[t] = fmaxf(acc, 0.f);
    __syncthreads();
    if (t < 128) {
        float a2 = b2c[t];
#pragma unroll 8
        for (int k = 0; k < 256; k++) a2 += hid[k] * W2c[t * 256 + k];
        g_cvec[t] = a2 + b2a[t] + b2b[t];
    }
}

__global__ void ef_prep_w(const float* __restrict__ W1a, const float* __restrict__ W2a,
                          const float* __restrict__ W1b, const float* __restrict__ W2b) {
    int i = blockIdx.x * 256 + threadIdx.x;
    if (i >= 32768) return;
    const float* Ws[2][2] = {{W1a, W2a}, {W1b, W2b}};
#pragma unroll
    for (int p = 0; p < 2; p++) {
        float w1 = Ws[p][0][i];
        __nv_bfloat16 h1 = __float2bfloat16(w1);
        g_wq[p][0][i] = h1;
        g_wq[p][1][i] = __float2bfloat16(w1 - __bfloat162float(h1));
        float w2 = Ws[p][1][i];
        __nv_bfloat16 h2 = __float2bfloat16(w2);
        g_wq[p][2][i] = h2;
        g_wq[p][3][i] = __float2bfloat16(w2 - __bfloat162float(h2));
    }
}

// ---------------- main fused kernel: one CTA = 128 edges ----------------
__global__ __launch_bounds__(256, 1)
void ef_main_kernel(const float* __restrict__ nf,
                    const void*  __restrict__ eidx,
                    const float* __restrict__ ef,
                    const float* __restrict__ b1a,
                    const float* __restrict__ b1b,
                    float* __restrict__ outp) {
    extern __shared__ char smem[];
    uint32_t sbase;
    asm("{ .reg .u64 t; cvta.to.shared.u64 t, %1; cvt.u32.u64 %0, t; }"
        : "=r"(sbase) : "l"((const void*)smem));
    float* B1Sf = (float*)(smem + B1S_OFF);
    float* CVf  = (float*)(smem + CV_OFF);
    float* Sf   = (float*)(smem + S_OFF);

    const int tid  = threadIdx.x;
    const int wid  = tid >> 5;
    const int lane = tid & 31;
    const int wm = wid & 3, wn = wid >> 2;
    const int e0 = blockIdx.x * 128;

    // ldmatrix lane address components
    const uint32_t arow = (lane & 7) + ((lane >> 3) & 1) * 8;
    const uint32_t acol = (lane >> 4) * 16;
    const uint32_t brow = (lane & 7) + (lane >> 4) * 8;
    const uint32_t bcol = ((lane >> 3) & 1) * 16;
    const uint32_t a1off = (32 * wm + arow) * 272 + acol;
    const uint32_t b1off = (32 * wn + brow) * 272 + bcol;
    const uint32_t a2off = (32 * wm + arow) * 144 + acol;
    const uint32_t b2off = (64 * wn + brow) * 144 + bcol;

    float acc2[2][8][4];
#pragma unroll
    for (int i = 0; i < 2; i++)
#pragma unroll
        for (int j = 0; j < 8; j++)
#pragma unroll
            for (int c = 0; c < 4; c++) acc2[i][j][c] = 0.f;

#pragma unroll 1
    for (int pass = 0; pass < 2; pass++) {
        __syncthreads();   // previous pass finished reading X
        // ---- stage X hi/lo (thread = half-row) + biases ----
        {
            int m = tid >> 1;
            int c0 = (tid & 1) * 64;
            int e = min(e0 + m, N_EDGES - 1);
            const float *pa, *pb = nullptr;
            if (pass == 0) {
                int s, d;
                if (g_is64) {
                    const long long* p = (const long long*)eidx;
                    s = (int)p[e]; d = (int)p[N_EDGES + e];
                } else {
                    const int* p = (const int*)eidx;
                    s = p[e]; d = p[N_EDGES + e];
                }
                pa = nf + (size_t)s * 128;
                pb = nf + (size_t)d * 128;
            } else {
                pa = ef + (size_t)e * 128;
            }
            char* xh = smem + XH_OFF + m * 272;
            char* xl = smem + XL_OFF + m * 272;
#pragma unroll 4
            for (int c4 = 0; c4 < 16; c4++) {
                int c = c0 + c4 * 4;
                float4 a = *(const float4*)(pa + c);
                if (pass == 0) {
                    float4 b = *(const float4*)(pb + c);
                    a.x += b.x; a.y += b.y; a.z += b.z; a.w += b.w;
                }
                float hx = __bfloat162float(__float2bfloat16(a.x));
                float hy = __bfloat162float(__float2bfloat16(a.y));
                float hz = __bfloat162float(__float2bfloat16(a.z));
                float hw = __bfloat162float(__float2bfloat16(a.w));
                uint2 hp, lp;
                hp.x = pack2(a.x, a.y); hp.y = pack2(a.z, a.w);
                lp.x = pack2(a.x - hx, a.y - hy); lp.y = pack2(a.z - hz, a.w - hw);
                *(uint2*)(xh + 2 * c) = hp;
                *(uint2*)(xl + 2 * c) = lp;
            }
            B1Sf[tid] = (pass ? b1b : b1a)[tid];
            if (pass == 0 && tid < 128) CVf[tid] = g_cvec[tid];
        }

#pragma unroll 1
        for (int chunk = 0; chunk < 4; chunk++) {
            const int hb = chunk * 64;
            __syncthreads();   // W buffers free, X/prev H consumed
            // ---- stage W1 chunk [64][128] hi/lo ----
            {
                const __nv_bfloat16* w1h = g_wq[pass][0];
                const __nv_bfloat16* w1l = g_wq[pass][1];
#pragma unroll
                for (int q = 0; q < 4; q++) {
                    int f = tid + q * 256;            // 1024 uint4
                    int row = f >> 4, c = f & 15;
                    *(uint4*)(smem + W1H_OFF + row * 272 + c * 16) =
                        *(const uint4*)(w1h + (size_t)(hb + row) * 128 + c * 8);
                    *(uint4*)(smem + W1L_OFF + row * 272 + c * 16) =
                        *(const uint4*)(w1l + (size_t)(hb + row) * 128 + c * 8);
                }
                const __nv_bfloat16* w2h = g_wq[pass][2];
                const __nv_bfloat16* w2l = g_wq[pass][3];
#pragma unroll
                for (int q = 0; q < 4; q++) {
                    int f = tid + q * 256;            // 1024 uint4
                    int row = f >> 3, c = f & 7;
                    *(uint4*)(smem + W2H_OFF + row * 144 + c * 16) =
                        *(const uint4*)(w2h + (size_t)row * 256 + hb + c * 8);
                    *(uint4*)(smem + W2L_OFF + row * 144 + c * 16) =
                        *(const uint4*)(w2l + (size_t)row * 256 + hb + c * 8);
                }
            }
            __syncthreads();

            // ---- GEMM1: H[128,64] = X @ W1c^T, 3 splits, K=128 ----
            float acc1[2][4][4];
#pragma unroll
            for (int i = 0; i < 2; i++)
#pragma unroll
                for (int j = 0; j < 4; j++)
#pragma unroll
                    for (int c = 0; c < 4; c++) acc1[i][j][c] = 0.f;
#pragma unroll
            for (int sp = 0; sp < 3; sp++) {
                uint32_t ab = sbase + (sp == 2 ? XL_OFF : XH_OFF) + a1off;
                uint32_t bb = sbase + (sp == 1 ? W1L_OFF : W1H_OFF) + b1off;
#pragma unroll
                for (int ks = 0; ks < 8; ks++) {
                    uint32_t a[2][4], b[2][4];
                    ldsm4(a[0], ab + ks * 32);
                    ldsm4(a[1], ab + ks * 32 + 16 * 272);
                    ldsm4(b[0], bb + ks * 32);
                    ldsm4(b[1], bb + ks * 32 + 16 * 272);
#pragma unroll
                    for (int mt = 0; mt < 2; mt++)
#pragma unroll
                        for (int nt = 0; nt < 4; nt++)
                            mma16816(acc1[mt][nt], a[mt],
                                     b[nt >> 1][(nt & 1) * 2], b[nt >> 1][(nt & 1) * 2 + 1]);
                }
            }
            // ---- bias + relu + split -> H hi/lo ----
            {
                int g = lane >> 2, i2 = (lane & 3) * 2;
#pragma unroll
                for (int mt = 0; mt < 2; mt++)
#pragma unroll
                    for (int nt = 0; nt < 4; nt++) {
                        int row = 32 * wm + 16 * mt + g;
                        int col = 32 * wn + 8 * nt + i2;
                        float bb0 = B1Sf[hb + col], bb1 = B1Sf[hb + col + 1];
                        float v0 = fmaxf(acc1[mt][nt][0] + bb0, 0.f);
                        float v1 = fmaxf(acc1[mt][nt][1] + bb1, 0.f);
                        float v2 = fmaxf(acc1[mt][nt][2] + bb0, 0.f);
                        float v3 = fmaxf(acc1[mt][nt][3] + bb1, 0.f);
                        float h0 = __bfloat162float(__float2bfloat16(v0));
                        float h1 = __bfloat162float(__float2bfloat16(v1));
                        float h2 = __bfloat162float(__float2bfloat16(v2));
                        float h3 = __bfloat162float(__float2bfloat16(v3));
                        *(uint32_t*)(smem + HH_OFF + row * 144 + col * 2) = pack2(v0, v1);
                        *(uint32_t*)(smem + HL_OFF + row * 144 + col * 2) = pack2(v0 - h0, v1 - h1);
                        *(uint32_t*)(smem + HH_OFF + (row + 8) * 144 + col * 2) = pack2(v2, v3);
                        *(uint32_t*)(smem + HL_OFF + (row + 8) * 144 + col * 2) = pack2(v2 - h2, v3 - h3);
                    }
            }
            __syncthreads();

            // ---- GEMM2: S += H @ W2c^T, 3 splits, K=64 ----
#pragma unroll
            for (int sp = 0; sp < 3; sp++) {
                uint32_t ab = sbase + (sp == 2 ? HL_OFF : HH_OFF) + a2off;
                uint32_t bb = sbase + (sp == 1 ? W2L_OFF : W2H_OFF) + b2off;
#pragma unroll
                for (int ks = 0; ks < 4; ks++) {
                    uint32_t a[2][4], b[4][4];
                    ldsm4(a[0], ab + ks * 32);
                    ldsm4(a[1], ab + ks * 32 + 16 * 144);
#pragma unroll
                    for (int p = 0; p < 4; p++)
                        ldsm4(b[p], bb + ks * 32 + p * 16 * 144);
#pragma unroll
                    for (int mt = 0; mt < 2; mt++)
#pragma unroll
                        for (int nt = 0; nt < 8; nt++)
                            mma16816(acc2[mt][nt], a[mt],
                                     b[nt >> 1][(nt & 1) * 2], b[nt >> 1][(nt & 1) * 2 + 1]);
                }
            }
        }
    }
    __syncthreads();   // all GEMMs done; W1/H/W2 areas free for S

    // ---- write S to smem (stride 132 floats = 528B, 16-aligned) ----
    {
        int g = lane >> 2, i2 = (lane & 3) * 2;
#pragma unroll
        for (int mt = 0; mt < 2; mt++)
#pragma unroll
            for (int nt = 0; nt < 8; nt++) {
                int row = 32 * wm + 16 * mt + g;
                int col = 64 * wn + 8 * nt + i2;
                Sf[row * 132 + col]       = acc2[mt][nt][0];
                Sf[row * 132 + col + 1]   = acc2[mt][nt][1];
                Sf[(row + 8) * 132 + col]     = acc2[mt][nt][2];
                Sf[(row + 8) * 132 + col + 1] = acc2[mt][nt][3];
            }
    }
    __syncthreads();

    // ---- per-row: +cvec, IN, dropout, relu ----
    if (tid < 128) {
        int m = tid;
        int e = min(e0 + m, N_EDGES - 1);
        float* Sr = Sf + m * 132;
        float sum = 0.f, sq = 0.f;
#pragma unroll 8
        for (int p = 0; p < 64; p++) {
            float2 v = *(float2*)(Sr + 2 * p);
            v.x += CVf[2 * p]; v.y += CVf[2 * p + 1];
            *(float2*)(Sr + 2 * p) = v;
            sum += v.x + v.y;
            sq  += v.x * v.x + v.y * v.y;
        }
        float mean = sum * 0.0078125f;
        float var  = sq * 0.0078125f - mean * mean;
        float rstd = rsqrtf(fmaxf(var, 0.f) + 1e-5f);
        unsigned mw[4];
#pragma unroll
        for (int i = 0; i < 4; i++) mw[i] = g_mask[4 * e + i];
#pragma unroll 8
        for (int p = 0; p < 64; p++) {
            int c0 = 2 * p, c1 = 2 * p + 1;
            float2 v = *(float2*)(Sr + c0);
            float x = (v.x - mean) * rstd;
            x = ((mw[c0 >> 5] >> (c0 & 31)) & 1u) ? x * (1.f / 0.9f) : 0.f;
            float y = (v.y - mean) * rstd;
            y = ((mw[c1 >> 5] >> (c1 & 31)) & 1u) ? y * (1.f / 0.9f) : 0.f;
            v.x = fmaxf(x, 0.f); v.y = fmaxf(y, 0.f);
            *(float2*)(Sr + c0) = v;
        }
    }
    __syncthreads();

    // ---- coalesced store with residual ----
#pragma unroll 4
    for (int q = 0; q < 16; q++) {
        int f = tid + q * 256;                 // 4096 float4
        int m = f >> 5, c4 = (f & 31) << 2;
        int e = e0 + m;
        if (e < N_EDGES) {
            float4 s = *(float4*)(Sf + m * 132 + c4);
            float4 ev = *(const float4*)(ef + (size_t)e * 128 + c4);
            s.x += ev.x; s.y += ev.y; s.z += ev.z; s.w += ev.w;
            *(float4*)(outp + (size_t)e * 128 + c4) = s;
        }
    }
}

extern "C" void kernel_launch(void* const* d_in, const int* in_sizes, int n_in,
                              void* d_out, int out_size) {
    const float* nf  = (const float*)d_in[0];
    const void*  ei  = d_in[1];
    const float* ef  = (const float*)d_in[2];
    const float* gf  = (const float*)d_in[3];
    const float* W1a = (const float*)d_in[4];
    const float* b1a = (const float*)d_in[5];
    const float* W2a = (const float*)d_in[6];
    const float* b2a = (const float*)d_in[7];
    const float* W1b = (const float*)d_in[8];
    const float* b1b = (const float*)d_in[9];
    const float* W2b = (const float*)d_in[10];
    const float* b2b = (const float*)d_in[11];
    const float* W1c = (const float*)d_in[12];
    const float* b1c = (const float*)d_in[13];
    const float* W2c = (const float*)d_in[14];
    const float* b2c = (const float*)d_in[15];
    float* out = (float*)d_out;

    ef_mask_kernel<<<(MASK_WORDS + 255) / 256, 256>>>();
    ef_detect_kernel<<<1, 32>>>((const unsigned*)ei);
    ef_hglob_kernel<<<1, 256>>>(gf, W1c, b1c, W2c, b2c, b2a, b2b);
    ef_prep_w<<<128, 256>>>(W1a, W2a, W1b, W2b);

    cudaFuncSetAttribute(ef_main_kernel,
                         cudaFuncAttributeMaxDynamicSharedMemorySize, SMEM_BYTES);
    ef_main_kernel<<<GRID_MAIN, 256, SMEM_BYTES>>>(nf, ei, ef, b1a, b1b, out);
}

// round 7
// speedup vs baseline: 2.7909x; 1.2462x over previous
#include <cuda_runtime.h>
#include <cuda_fp16.h>
#include <cstdint>

#define N_NODES   50000
#define N_EDGES   500000
#define MASK_WORDS 2000000
#define GRID_MAIN 3907

// smem byte offsets
#define XH_OFF   0          // [128 m][128 k] fp16, row stride 272B
#define XL_OFF   34816
#define W1_OFF   69632      // [64 n][128 k] fp16 chunk, stride 272B
#define HH_OFF   87040      // [128 m][64 k] fp16, stride 144B
#define HL_OFF   105472
#define W2_OFF   123904     // [128 n][64 k] fp16 chunk, stride 144B
#define B1S_OFF  142336     // 256 floats
#define CV_OFF   143360     // 128 floats
#define S_OFF    69632      // fp32 [128][132] (reuses W1/HH/HL area post-GEMM)
#define SMEM_BYTES 143872

__device__ unsigned g_mask[MASK_WORDS];
__device__ float    g_cvec[128];
__device__ int      g_is64;
__device__ __align__(16) __half g_wq[2][2][32768]; // [pass][W1,W2] fp16

// ---------------- mma helpers ----------------
__device__ __forceinline__ void ldsm4(uint32_t* r, uint32_t addr) {
    asm volatile("ldmatrix.sync.aligned.m8n8.x4.shared.b16 {%0,%1,%2,%3}, [%4];"
        : "=r"(r[0]), "=r"(r[1]), "=r"(r[2]), "=r"(r[3]) : "r"(addr));
}
__device__ __forceinline__ void mma16816(float* d, const uint32_t* a,
                                         uint32_t b0, uint32_t b1) {
    asm volatile("mma.sync.aligned.m16n8k16.row.col.f32.f16.f16.f32 "
        "{%0,%1,%2,%3}, {%4,%5,%6,%7}, {%8,%9}, {%0,%1,%2,%3};"
        : "+f"(d[0]), "+f"(d[1]), "+f"(d[2]), "+f"(d[3])
        : "r"(a[0]), "r"(a[1]), "r"(a[2]), "r"(a[3]), "r"(b0), "r"(b1));
}
__device__ __forceinline__ uint32_t pack2h(float v0, float v1) {
    return ((uint32_t)__half_as_ushort(__float2half(v1)) << 16) |
           (uint32_t)__half_as_ushort(__float2half(v0));
}

// ---------------- threefry (JAX partitionable, key (0,42)) ----------------
__device__ __forceinline__ unsigned rotl32(unsigned x, int d) {
    return __funnelshift_l(x, x, d);
}
__device__ __forceinline__ void threefry(unsigned c0, unsigned c1,
                                         unsigned &o0, unsigned &o1) {
    const unsigned k0 = 0u, k1 = 42u, k2 = 0x1BD11BDAu ^ 42u;
    unsigned x0 = c0 + k0, x1 = c1 + k1;
#define TF4(ra, rb, rc, rd)                                  \
    x0 += x1; x1 = rotl32(x1, ra); x1 ^= x0;                 \
    x0 += x1; x1 = rotl32(x1, rb); x1 ^= x0;                 \
    x0 += x1; x1 = rotl32(x1, rc); x1 ^= x0;                 \
    x0 += x1; x1 = rotl32(x1, rd); x1 ^= x0;
    TF4(13, 15, 26, 6)  x0 += k1; x1 += k2 + 1u;
    TF4(17, 29, 16, 24) x0 += k2; x1 += k0 + 2u;
    TF4(13, 15, 26, 6)  x0 += k0; x1 += k1 + 3u;
    TF4(17, 29, 16, 24) x0 += k1; x1 += k2 + 4u;
    TF4(13, 15, 26, 6)  x0 += k2; x1 += k0 + 5u;
#undef TF4
    o0 = x0; o1 = x1;
}

__global__ void ef_mask_kernel() {
    int t = blockIdx.x * blockDim.x + threadIdx.x;
    if (t >= MASK_WORDS) return;
    unsigned base = (unsigned)t * 32u;
    unsigned w = 0u;
#pragma unroll 4
    for (int k = 0; k < 32; k++) {
        unsigned o0, o1;
        threefry(0u, base + k, o0, o1);
        w |= ((unsigned)(((o0 ^ o1) >> 9) < 7549747u)) << k;
    }
    g_mask[t] = w;
}

__global__ void ef_detect_kernel(const unsigned* __restrict__ ei) {
    unsigned v = ei[2 * threadIdx.x + 1];
    unsigned b = __ballot_sync(0xffffffffu, v == 0u);
    if (threadIdx.x == 0) g_is64 = (b == 0xffffffffu) ? 1 : 0;
}

__global__ void ef_hglob_kernel(const float* __restrict__ gf,
                                const float* __restrict__ W1c, const float* __restrict__ b1c,
                                const float* __restrict__ W2c, const float* __restrict__ b2c,
                                const float* __restrict__ b2a, const float* __restrict__ b2b) {
    __shared__ float sg[128];
    __shared__ float hid[256];
    int t = threadIdx.x;
    if (t < 128) sg[t] = gf[t];
    __syncthreads();
    float acc = b1c[t];
#pragma unroll 8
    for (int k = 0; k < 128; k++) acc += sg[k] * W1c[t * 128 + k];
    hid[t] = fmaxf(acc, 0.f);
    __syncthreads();
    if (t < 128) {
        float a2 = b2c[t];
#pragma unroll 8
        for (int k = 0; k < 256; k++) a2 += hid[k] * W2c[t * 256 + k];
        g_cvec[t] = a2 + b2a[t] + b2b[t];
    }
}

__global__ void ef_prep_w(const float* __restrict__ W1a, const float* __restrict__ W2a,
                          const float* __restrict__ W1b, const float* __restrict__ W2b) {
    int i = blockIdx.x * 256 + threadIdx.x;
    if (i >= 32768) return;
    g_wq[0][0][i] = __float2half(W1a[i]);
    g_wq[0][1][i] = __float2half(W2a[i]);
    g_wq[1][0][i] = __float2half(W1b[i]);
    g_wq[1][1][i] = __float2half(W2b[i]);
}

// ---------------- main fused kernel: one CTA = 128 edges ----------------
__global__ __launch_bounds__(256, 1)
void ef_main_kernel(const float* __restrict__ nf,
                    const void*  __restrict__ eidx,
                    const float* __restrict__ ef,
                    const float* __restrict__ b1a,
                    const float* __restrict__ b1b,
                    float* __restrict__ outp) {
    extern __shared__ char smem[];
    uint32_t sbase;
    asm("{ .reg .u64 t; cvta.to.shared.u64 t, %1; cvt.u32.u64 %0, t; }"
        : "=r"(sbase) : "l"((const void*)smem));
    float* B1Sf = (float*)(smem + B1S_OFF);
    float* CVf  = (float*)(smem + CV_OFF);
    float* Sf   = (float*)(smem + S_OFF);

    const int tid  = threadIdx.x;
    const int wid  = tid >> 5;
    const int lane = tid & 31;
    const int wm = wid & 3, wn = wid >> 2;
    const int e0 = blockIdx.x * 128;

    // ldmatrix lane address components
    const uint32_t arow = (lane & 7) + ((lane >> 3) & 1) * 8;
    const uint32_t acol = (lane >> 4) * 16;
    const uint32_t brow = (lane & 7) + (lane >> 4) * 8;
    const uint32_t bcol = ((lane >> 3) & 1) * 16;
    const uint32_t a1off = (32 * wm + arow) * 272 + acol;
    const uint32_t b1off = (32 * wn + brow) * 272 + bcol;
    const uint32_t a2off = (32 * wm + arow) * 144 + acol;
    const uint32_t b2off = (64 * wn + brow) * 144 + bcol;

    float acc2[2][8][4];
#pragma unroll
    for (int i = 0; i < 2; i++)
#pragma unroll
        for (int j = 0; j < 8; j++)
#pragma unroll
            for (int c = 0; c < 4; c++) acc2[i][j][c] = 0.f;

#pragma unroll 1
    for (int pass = 0; pass < 2; pass++) {
        __syncthreads();   // previous pass finished reading X
        // ---- stage X hi/lo fp16 (thread = half-row) + biases ----
        {
            int m = tid >> 1;
            int c0 = (tid & 1) * 64;
            int e = min(e0 + m, N_EDGES - 1);
            const float *pa, *pb = nullptr;
            if (pass == 0) {
                int s, d;
                if (g_is64) {
                    const long long* p = (const long long*)eidx;
                    s = (int)p[e]; d = (int)p[N_EDGES + e];
                } else {
                    const int* p = (const int*)eidx;
                    s = p[e]; d = p[N_EDGES + e];
                }
                pa = nf + (size_t)s * 128;
                pb = nf + (size_t)d * 128;
            } else {
                pa = ef + (size_t)e * 128;
            }
            char* xh = smem + XH_OFF + m * 272;
            char* xl = smem + XL_OFF + m * 272;
#pragma unroll 4
            for (int c4 = 0; c4 < 16; c4++) {
                int c = c0 + c4 * 4;
                float4 a = *(const float4*)(pa + c);
                if (pass == 0) {
                    float4 b = *(const float4*)(pb + c);
                    a.x += b.x; a.y += b.y; a.z += b.z; a.w += b.w;
                }
                float hx = __half2float(__float2half(a.x));
                float hy = __half2float(__float2half(a.y));
                float hz = __half2float(__float2half(a.z));
                float hw = __half2float(__float2half(a.w));
                uint2 hp, lp;
                hp.x = pack2h(a.x, a.y); hp.y = pack2h(a.z, a.w);
                lp.x = pack2h(a.x - hx, a.y - hy); lp.y = pack2h(a.z - hz, a.w - hw);
                *(uint2*)(xh + 2 * c) = hp;
                *(uint2*)(xl + 2 * c) = lp;
            }
            B1Sf[tid] = (pass ? b1b : b1a)[tid];
            if (pass == 0 && tid < 128) CVf[tid] = g_cvec[tid];
        }

#pragma unroll 1
        for (int chunk = 0; chunk < 4; chunk++) {
            const int hb = chunk * 64;
            __syncthreads();   // W buffers free, X/prev H consumed
            // ---- stage W1 chunk [64][128] fp16 ----
            {
                const __half* w1 = g_wq[pass][0];
#pragma unroll
                for (int q = 0; q < 4; q++) {
                    int f = tid + q * 256;            // 1024 uint4
                    int row = f >> 4, c = f & 15;
                    *(uint4*)(smem + W1_OFF + row * 272 + c * 16) =
                        *(const uint4*)(w1 + (size_t)(hb + row) * 128 + c * 8);
                }
                const __half* w2 = g_wq[pass][1];
#pragma unroll
                for (int q = 0; q < 4; q++) {
                    int f = tid + q * 256;            // 1024 uint4
                    int row = f >> 3, c = f & 7;
                    *(uint4*)(smem + W2_OFF + row * 144 + c * 16) =
                        *(const uint4*)(w2 + (size_t)row * 256 + hb + c * 8);
                }
            }
            __syncthreads();

            // ---- GEMM1: H[128,64] = X @ W1c^T, 2 splits (Xh,Xl), K=128 ----
            float acc1[2][4][4];
#pragma unroll
            for (int i = 0; i < 2; i++)
#pragma unroll
                for (int j = 0; j < 4; j++)
#pragma unroll
                    for (int c = 0; c < 4; c++) acc1[i][j][c] = 0.f;
#pragma unroll
            for (int sp = 0; sp < 2; sp++) {
                uint32_t ab = sbase + (sp ? XL_OFF : XH_OFF) + a1off;
                uint32_t bb = sbase + W1_OFF + b1off;
#pragma unroll
                for (int ks = 0; ks < 8; ks++) {
                    uint32_t a[2][4], b[2][4];
                    ldsm4(a[0], ab + ks * 32);
                    ldsm4(a[1], ab + ks * 32 + 16 * 272);
                    ldsm4(b[0], bb + ks * 32);
                    ldsm4(b[1], bb + ks * 32 + 16 * 272);
#pragma unroll
                    for (int mt = 0; mt < 2; mt++)
#pragma unroll
                        for (int nt = 0; nt < 4; nt++)
                            mma16816(acc1[mt][nt], a[mt],
                                     b[nt >> 1][(nt & 1) * 2], b[nt >> 1][(nt & 1) * 2 + 1]);
                }
            }
            // ---- bias + relu + split -> H hi/lo fp16 ----
            {
                int g = lane >> 2, i2 = (lane & 3) * 2;
#pragma unroll
                for (int mt = 0; mt < 2; mt++)
#pragma unroll
                    for (int nt = 0; nt < 4; nt++) {
                        int row = 32 * wm + 16 * mt + g;
                        int col = 32 * wn + 8 * nt + i2;
                        float bb0 = B1Sf[hb + col], bb1 = B1Sf[hb + col + 1];
                        float v0 = fmaxf(acc1[mt][nt][0] + bb0, 0.f);
                        float v1 = fmaxf(acc1[mt][nt][1] + bb1, 0.f);
                        float v2 = fmaxf(acc1[mt][nt][2] + bb0, 0.f);
                        float v3 = fmaxf(acc1[mt][nt][3] + bb1, 0.f);
                        float h0 = __half2float(__float2half(v0));
                        float h1 = __half2float(__float2half(v1));
                        float h2 = __half2float(__float2half(v2));
                        float h3 = __half2float(__float2half(v3));
                        *(uint32_t*)(smem + HH_OFF + row * 144 + col * 2) = pack2h(v0, v1);
                        *(uint32_t*)(smem + HL_OFF + row * 144 + col * 2) = pack2h(v0 - h0, v1 - h1);
                        *(uint32_t*)(smem + HH_OFF + (row + 8) * 144 + col * 2) = pack2h(v2, v3);
                        *(uint32_t*)(smem + HL_OFF + (row + 8) * 144 + col * 2) = pack2h(v2 - h2, v3 - h3);
                    }
            }
            __syncthreads();

            // ---- GEMM2: S += H @ W2c^T, 2 splits (Hh,Hl), K=64 ----
#pragma unroll
            for (int sp = 0; sp < 2; sp++) {
                uint32_t ab = sbase + (sp ? HL_OFF : HH_OFF) + a2off;
                uint32_t bb = sbase + W2_OFF + b2off;
#pragma unroll
                for (int ks = 0; ks < 4; ks++) {
                    uint32_t a[2][4], b[4][4];
                    ldsm4(a[0], ab + ks * 32);
                    ldsm4(a[1], ab + ks * 32 + 16 * 144);
#pragma unroll
                    for (int p = 0; p < 4; p++)
                        ldsm4(b[p], bb + ks * 32 + p * 16 * 144);
#pragma unroll
                    for (int mt = 0; mt < 2; mt++)
#pragma unroll
                        for (int nt = 0; nt < 8; nt++)
                            mma16816(acc2[mt][nt], a[mt],
                                     b[nt >> 1][(nt & 1) * 2], b[nt >> 1][(nt & 1) * 2 + 1]);
                }
            }
        }
    }
    __syncthreads();   // all GEMMs done; W1/H areas free for S

    // ---- write S to smem (stride 132 floats = 528B, 16-aligned) ----
    {
        int g = lane >> 2, i2 = (lane & 3) * 2;
#pragma unroll
        for (int mt = 0; mt < 2; mt++)
#pragma unroll
            for (int nt = 0; nt < 8; nt++) {
                int row = 32 * wm + 16 * mt + g;
                int col = 64 * wn + 8 * nt + i2;
                Sf[row * 132 + col]       = acc2[mt][nt][0];
                Sf[row * 132 + col + 1]   = acc2[mt][nt][1];
                Sf[(row + 8) * 132 + col]     = acc2[mt][nt][2];
                Sf[(row + 8) * 132 + col + 1] = acc2[mt][nt][3];
            }
    }
    __syncthreads();

    // ---- per-row: +cvec, IN, dropout, relu ----
    if (tid < 128) {
        int m = tid;
        int e = min(e0 + m, N_EDGES - 1);
        float* Sr = Sf + m * 132;
        float sum = 0.f, sq = 0.f;
#pragma unroll 8
        for (int p = 0; p < 64; p++) {
            float2 v = *(float2*)(Sr + 2 * p);
            v.x += CVf[2 * p]; v.y += CVf[2 * p + 1];
            *(float2*)(Sr + 2 * p) = v;
            sum += v.x + v.y;
            sq  += v.x * v.x + v.y * v.y;
        }
        float mean = sum * 0.0078125f;
        float var  = sq * 0.0078125f - mean * mean;
        float rstd = rsqrtf(fmaxf(var, 0.f) + 1e-5f);
        unsigned mw[4];
#pragma unroll
        for (int i = 0; i < 4; i++) mw[i] = g_mask[4 * e + i];
#pragma unroll 8
        for (int p = 0; p < 64; p++) {
            int c0 = 2 * p, c1 = 2 * p + 1;
            float2 v = *(float2*)(Sr + c0);
            float x = (v.x - mean) * rstd;
            x = ((mw[c0 >> 5] >> (c0 & 31)) & 1u) ? x * (1.f / 0.9f) : 0.f;
            float y = (v.y - mean) * rstd;
            y = ((mw[c1 >> 5] >> (c1 & 31)) & 1u) ? y * (1.f / 0.9f) : 0.f;
            v.x = fmaxf(x, 0.f); v.y = fmaxf(y, 0.f);
            *(float2*)(Sr + c0) = v;
        }
    }
    __syncthreads();

    // ---- coalesced store with residual ----
#pragma unroll 4
    for (int q = 0; q < 16; q++) {
        int f = tid + q * 256;                 // 4096 float4
        int m = f >> 5, c4 = (f & 31) << 2;
        int e = e0 + m;
        if (e < N_EDGES) {
            float4 s = *(float4*)(Sf + m * 132 + c4);
            float4 ev = *(const float4*)(ef + (size_t)e * 128 + c4);
            s.x += ev.x; s.y += ev.y; s.z += ev.z; s.w += ev.w;
            *(float4*)(outp + (size_t)e * 128 + c4) = s;
        }
    }
}

extern "C" void kernel_launch(void* const* d_in, const int* in_sizes, int n_in,
                              void* d_out, int out_size) {
    const float* nf  = (const float*)d_in[0];
    const void*  ei  = d_in[1];
    const float* ef  = (const float*)d_in[2];
    const float* gf  = (const float*)d_in[3];
    const float* W1a = (const float*)d_in[4];
    const float* b1a = (const float*)d_in[5];
    const float* W2a = (const float*)d_in[6];
    const float* b2a = (const float*)d_in[7];
    const float* W1b = (const float*)d_in[8];
    const float* b1b = (const float*)d_in[9];
    const float* W2b = (const float*)d_in[10];
    const float* b2b = (const float*)d_in[11];
    const float* W1c = (const float*)d_in[12];
    const float* b1c = (const float*)d_in[13];
    const float* W2c = (const float*)d_in[14];
    const float* b2c = (const float*)d_in[15];
    float* out = (float*)d_out;

    ef_mask_kernel<<<(MASK_WORDS + 255) / 256, 256>>>();
    ef_detect_kernel<<<1, 32>>>((const unsigned*)ei);
    ef_hglob_kernel<<<1, 256>>>(gf, W1c, b1c, W2c, b2c, b2a, b2b);
    ef_prep_w<<<128, 256>>>(W1a, W2a, W1b, W2b);

    cudaFuncSetAttribute(ef_main_kernel,
                         cudaFuncAttributeMaxDynamicSharedMemorySize, SMEM_BYTES);
    ef_main_kernel<<<GRID_MAIN, 256, SMEM_BYTES>>>(nf, ei, ef, b1a, b1b, out);
}

// round 10
// speedup vs baseline: 2.8236x; 1.0117x over previous
#include <cuda_runtime.h>
#include <cuda_fp16.h>
#include <cstdint>

#define N_NODES   50000
#define N_EDGES   500000
#define MASK_WORDS 2000000
#define GRID_MAIN 3907
#define GRID_P    391

// smem byte offsets (main kernel)
#define XH_OFF   0          // [128 m][128 k] fp16, row stride 272B
#define XL_OFF   34816
#define W1_OFF   69632      // [64 n][128 k] fp16 chunk, stride 272B
#define HH_OFF   87040      // [128 m][64 k] fp16, stride 144B
#define HL_OFF   105472
#define W2_OFF   123904     // [128 n][64 k] fp16 chunk, stride 144B
#define B1S_OFF  142336     // 256 floats
#define CV_OFF   143360     // 128 floats
#define SIDX_OFF 143872     // 256 ints
#define S_OFF    69632      // fp32 [128][132] (reuses W1/HH/HL area post-GEMM)
#define SMEM_BYTES 144896
#define SMEM_BYTES_P 104448 // prep_p: XH/XL + W1 only

__device__ unsigned g_mask[MASK_WORDS];
__device__ float    g_cvec[128];
__device__ int      g_is64;
__device__ __align__(16) __half g_wq[2][2][32768]; // [pass][W1,W2] fp16
__device__ __align__(16) float  g_P[(size_t)N_NODES * 256]; // nf @ W1a^T

// ---------------- mma helpers ----------------
__device__ __forceinline__ void ldsm4(uint32_t* r, uint32_t addr) {
    asm volatile("ldmatrix.sync.aligned.m8n8.x4.shared.b16 {%0,%1,%2,%3}, [%4];"
        : "=r"(r[0]), "=r"(r[1]), "=r"(r[2]), "=r"(r[3]) : "r"(addr));
}
__device__ __forceinline__ void mma16816(float* d, const uint32_t* a,
                                         uint32_t b0, uint32_t b1) {
    asm volatile("mma.sync.aligned.m16n8k16.row.col.f32.f16.f16.f32 "
        "{%0,%1,%2,%3}, {%4,%5,%6,%7}, {%8,%9}, {%0,%1,%2,%3};"
        : "+f"(d[0]), "+f"(d[1]), "+f"(d[2]), "+f"(d[3])
        : "r"(a[0]), "r"(a[1]), "r"(a[2]), "r"(a[3]), "r"(b0), "r"(b1));
}
__device__ __forceinline__ uint32_t pack2h(float v0, float v1) {
    return ((uint32_t)__half_as_ushort(__float2half(v1)) << 16) |
           (uint32_t)__half_as_ushort(__float2half(v0));
}

// ---------------- threefry (JAX partitionable, key (0,42)) ----------------
__device__ __forceinline__ unsigned rotl32(unsigned x, int d) {
    return __funnelshift_l(x, x, d);
}
__device__ __forceinline__ void threefry(unsigned c0, unsigned c1,
                                         unsigned &o0, unsigned &o1) {
    const unsigned k0 = 0u, k1 = 42u, k2 = 0x1BD11BDAu ^ 42u;
    unsigned x0 = c0 + k0, x1 = c1 + k1;
#define TF4(ra, rb, rc, rd)                                  \
    x0 += x1; x1 = rotl32(x1, ra); x1 ^= x0;                 \
    x0 += x1; x1 = rotl32(x1, rb); x1 ^= x0;                 \
    x0 += x1; x1 = rotl32(x1, rc); x1 ^= x0;                 \
    x0 += x1; x1 = rotl32(x1, rd); x1 ^= x0;
    TF4(13, 15, 26, 6)  x0 += k1; x1 += k2 + 1u;
    TF4(17, 29, 16, 24) x0 += k2; x1 += k0 + 2u;
    TF4(13, 15, 26, 6)  x0 += k0; x1 += k1 + 3u;
    TF4(17, 29, 16, 24) x0 += k1; x1 += k2 + 4u;
    TF4(13, 15, 26, 6)  x0 += k2; x1 += k0 + 5u;
#undef TF4
    o0 = x0; o1 = x1;
}

__global__ void ef_mask_kernel() {
    int t = blockIdx.x * blockDim.x + threadIdx.x;
    if (t >= MASK_WORDS) return;
    unsigned base = (unsigned)t * 32u;
    unsigned w = 0u;
#pragma unroll 4
    for (int k = 0; k < 32; k++) {
        unsigned o0, o1;
        threefry(0u, base + k, o0, o1);
        w |= ((unsigned)(((o0 ^ o1) >> 9) < 7549747u)) << k;
    }
    g_mask[t] = w;
}

__global__ void ef_detect_kernel(const unsigned* __restrict__ ei) {
    unsigned v = ei[2 * threadIdx.x + 1];
    unsigned b = __ballot_sync(0xffffffffu, v == 0u);
    if (threadIdx.x == 0) g_is64 = (b == 0xffffffffu) ? 1 : 0;
}

__global__ void ef_hglob_kernel(const float* __restrict__ gf,
                                const float* __restrict__ W1c, const float* __restrict__ b1c,
                                const float* __restrict__ W2c, const float* __restrict__ b2c,
                                const float* __restrict__ b2a, const float* __restrict__ b2b) {
    __shared__ float sg[128];
    __shared__ float hid[256];
    int t = threadIdx.x;
    if (t < 128) sg[t] = gf[t];
    __syncthreads();
    float acc = b1c[t];
#pragma unroll 8
    for (int k = 0; k < 128; k++) acc += sg[k] * W1c[t * 128 + k];
    hid[t] = fmaxf(acc, 0.f);
    __syncthreads();
    if (t < 128) {
        float a2 = b2c[t];
#pragma unroll 8
        for (int k = 0; k < 256; k++) a2 += hid[k] * W2c[t * 256 + k];
        g_cvec[t] = a2 + b2a[t] + b2b[t];
    }
}

__global__ void ef_prep_w(const float* __restrict__ W1a, const float* __restrict__ W2a,
                          const float* __restrict__ W1b, const float* __restrict__ W2b) {
    int i = blockIdx.x * 256 + threadIdx.x;
    if (i >= 32768) return;
    g_wq[0][0][i] = __float2half(W1a[i]);
    g_wq[0][1][i] = __float2half(W2a[i]);
    g_wq[1][0][i] = __float2half(W1b[i]);
    g_wq[1][1][i] = __float2half(W2b[i]);
}

// ---------------- P = nf @ W1a^T  (node table precompute) ----------------
__global__ __launch_bounds__(256, 1)
void ef_prep_p(const float* __restrict__ nf) {
    extern __shared__ char smem[];
    uint32_t sbase;
    asm("{ .reg .u64 t; cvta.to.shared.u64 t, %1; cvt.u32.u64 %0, t; }"
        : "=r"(sbase) : "l"((const void*)smem));

    const int tid  = threadIdx.x;
    const int wid  = tid >> 5;
    const int lane = tid & 31;
    const int wm = wid & 3, wn = wid >> 2;
    const int r0 = blockIdx.x * 128;

    const uint32_t arow = (lane & 7) + ((lane >> 3) & 1) * 8;
    const uint32_t acol = (lane >> 4) * 16;
    const uint32_t brow = (lane & 7) + (lane >> 4) * 8;
    const uint32_t bcol = ((lane >> 3) & 1) * 16;
    const uint32_t a1off = (32 * wm + arow) * 272 + acol;
    const uint32_t b1off = (32 * wn + brow) * 272 + bcol;

    // stage node rows (coalesced) as fp16 hi/lo
    {
        int m = tid >> 1;
        int c0 = (tid & 1) * 64;
        int node = min(r0 + m, N_NODES - 1);
        const float* pa = nf + (size_t)node * 128;
        char* xh = smem + XH_OFF + m * 272;
        char* xl = smem + XL_OFF + m * 272;
#pragma unroll 4
        for (int c4 = 0; c4 < 16; c4++) {
            int c = c0 + c4 * 4;
            float4 a = *(const float4*)(pa + c);
            float hx = __half2float(__float2half(a.x));
            float hy = __half2float(__float2half(a.y));
            float hz = __half2float(__float2half(a.z));
            float hw = __half2float(__float2half(a.w));
            uint2 hp, lp;
            hp.x = pack2h(a.x, a.y); hp.y = pack2h(a.z, a.w);
            lp.x = pack2h(a.x - hx, a.y - hy); lp.y = pack2h(a.z - hz, a.w - hw);
            *(uint2*)(xh + 2 * c) = hp;
            *(uint2*)(xl + 2 * c) = lp;
        }
    }

#pragma unroll 1
    for (int chunk = 0; chunk < 4; chunk++) {
        const int hb = chunk * 64;
        __syncthreads();
        // stage W1a chunk [64][128]
        {
            const __half* w1 = g_wq[0][0];
#pragma unroll
            for (int q = 0; q < 4; q++) {
                int f = tid + q * 256;
                int row = f >> 4, c = f & 15;
                *(uint4*)(smem + W1_OFF + row * 272 + c * 16) =
                    *(const uint4*)(w1 + (size_t)(hb + row) * 128 + c * 8);
            }
        }
        __syncthreads();

        float acc1[2][4][4];
#pragma unroll
        for (int i = 0; i < 2; i++)
#pragma unroll
            for (int j = 0; j < 4; j++)
#pragma unroll
                for (int c = 0; c < 4; c++) acc1[i][j][c] = 0.f;
#pragma unroll
        for (int sp = 0; sp < 2; sp++) {
            uint32_t ab = sbase + (sp ? XL_OFF : XH_OFF) + a1off;
            uint32_t bb = sbase + W1_OFF + b1off;
#pragma unroll
            for (int ks = 0; ks < 8; ks++) {
                uint32_t a[2][4], b[2][4];
                ldsm4(a[0], ab + ks * 32);
                ldsm4(a[1], ab + ks * 32 + 16 * 272);
                ldsm4(b[0], bb + ks * 32);
                ldsm4(b[1], bb + ks * 32 + 16 * 272);
#pragma unroll
                for (int mt = 0; mt < 2; mt++)
#pragma unroll
                    for (int nt = 0; nt < 4; nt++)
                        mma16816(acc1[mt][nt], a[mt],
                                 b[nt >> 1][(nt & 1) * 2], b[nt >> 1][(nt & 1) * 2 + 1]);
            }
        }
        // write P chunk (duplicate clamped rows write identical values)
        {
            int g = lane >> 2, i2 = (lane & 3) * 2;
#pragma unroll
            for (int mt = 0; mt < 2; mt++)
#pragma unroll
                for (int nt = 0; nt < 4; nt++) {
                    int row = 32 * wm + 16 * mt + g;
                    int col = 32 * wn + 8 * nt + i2;
                    int n1 = min(r0 + row, N_NODES - 1);
                    int n2 = min(r0 + row + 8, N_NODES - 1);
                    float2 v0; v0.x = acc1[mt][nt][0]; v0.y = acc1[mt][nt][1];
                    float2 v1; v1.x = acc1[mt][nt][2]; v1.y = acc1[mt][nt][3];
                    *(float2*)(g_P + (size_t)n1 * 256 + hb + col) = v0;
                    *(float2*)(g_P + (size_t)n2 * 256 + hb + col) = v1;
                }
        }
    }
}

// ---------------- main fused kernel: one CTA = 128 edges ----------------
__global__ __launch_bounds__(256, 1)
void ef_main_kernel(const void*  __restrict__ eidx,
                    const float* __restrict__ ef,
                    const float* __restrict__ b1a,
                    const float* __restrict__ b1b,
                    float* __restrict__ outp) {
    extern __shared__ char smem[];
    uint32_t sbase;
    asm("{ .reg .u64 t; cvta.to.shared.u64 t, %1; cvt.u32.u64 %0, t; }"
        : "=r"(sbase) : "l"((const void*)smem));
    float* B1Sf = (float*)(smem + B1S_OFF);
    float* CVf  = (float*)(smem + CV_OFF);
    int*   sidx = (int*)(smem + SIDX_OFF);
    float* Sf   = (float*)(smem + S_OFF);

    const int tid  = threadIdx.x;
    const int wid  = tid >> 5;
    const int lane = tid & 31;
    const int wm = wid & 3, wn = wid >> 2;
    const int e0 = blockIdx.x * 128;

    const uint32_t arow = (lane & 7) + ((lane >> 3) & 1) * 8;
    const uint32_t acol = (lane >> 4) * 16;
    const uint32_t brow = (lane & 7) + (lane >> 4) * 8;
    const uint32_t bcol = ((lane >> 3) & 1) * 16;
    const uint32_t a1off = (32 * wm + arow) * 272 + acol;
    const uint32_t b1off = (32 * wn + brow) * 272 + bcol;
    const uint32_t a2off = (32 * wm + arow) * 144 + acol;
    const uint32_t b2off = (64 * wn + brow) * 144 + bcol;

    // W staging coords (per thread, 4 quarters)
    int w2row[4], w2c[4];
#pragma unroll
    for (int q = 0; q < 4; q++) {
        int f = tid + q * 256;
        w2row[q] = f >> 3; w2c[q] = f & 7;
    }
    int w1row[4], w1c[4];
#pragma unroll
    for (int q = 0; q < 4; q++) {
        int f = tid + q * 256;
        w1row[q] = f >> 4; w1c[q] = f & 15;
    }

    // indices + biases + cvec
    if (tid < 128) {
        int e = min(e0 + tid, N_EDGES - 1);
        int s, d;
        if (g_is64) {
            const long long* p = (const long long*)eidx;
            s = (int)p[e]; d = (int)p[N_EDGES + e];
        } else {
            const int* p = (const int*)eidx;
            s = p[e]; d = p[N_EDGES + e];
        }
        sidx[tid] = s; sidx[128 + tid] = d;
        CVf[tid] = g_cvec[tid];
    }
    B1Sf[tid] = b1a[tid];

    float acc2[2][8][4];
#pragma unroll
    for (int i = 0; i < 2; i++)
#pragma unroll
        for (int j = 0; j < 8; j++)
#pragma unroll
            for (int c = 0; c < 4; c++) acc2[i][j][c] = 0.f;

    // =================== pass a: gather P + GEMM2 only ===================
    {
        const __half* w2 = g_wq[0][1];
        uint4 rw2[4];
#pragma unroll
        for (int q = 0; q < 4; q++)
            rw2[q] = *(const uint4*)(w2 + (size_t)w2row[q] * 256 + 0 + w2c[q] * 8);

#pragma unroll 1
        for (int chunk = 0; chunk < 4; chunk++) {
            const int hb = chunk * 64;
            __syncthreads();   // W2/H free (prev GEMM2 done); first iter: sidx/B1S ready
#pragma unroll
            for (int q = 0; q < 4; q++)
                *(uint4*)(smem + W2_OFF + w2row[q] * 144 + w2c[q] * 16) = rw2[q];
            if (chunk < 3) {
#pragma unroll
                for (int q = 0; q < 4; q++)
                    rw2[q] = *(const uint4*)(w2 + (size_t)w2row[q] * 256 + hb + 64 + w2c[q] * 8);
            }
            // gather H chunk = relu(P[src]+P[dst]+b1a) -> hi/lo fp16
            {
                int m = tid >> 1;
                int c0 = (tid & 1) * 32;
                const float* ps = g_P + (size_t)sidx[m] * 256 + hb + c0;
                const float* pd = g_P + (size_t)sidx[128 + m] * 256 + hb + c0;
                char* hh = smem + HH_OFF + m * 144;
                char* hl = smem + HL_OFF + m * 144;
#pragma unroll
                for (int j4 = 0; j4 < 8; j4++) {
                    int col = c0 + 4 * j4;
                    float4 a = *(const float4*)(ps + 4 * j4);
                    float4 b = *(const float4*)(pd + 4 * j4);
                    float v0 = fmaxf(a.x + b.x + B1Sf[hb + col],     0.f);
                    float v1 = fmaxf(a.y + b.y + B1Sf[hb + col + 1], 0.f);
                    float v2 = fmaxf(a.z + b.z + B1Sf[hb + col + 2], 0.f);
                    float v3 = fmaxf(a.w + b.w + B1Sf[hb + col + 3], 0.f);
                    float h0 = __half2float(__float2half(v0));
                    float h1 = __half2float(__float2half(v1));
                    float h2 = __half2float(__float2half(v2));
                    float h3 = __half2float(__float2half(v3));
                    uint2 hp, lp;
                    hp.x = pack2h(v0, v1); hp.y = pack2h(v2, v3);
                    lp.x = pack2h(v0 - h0, v1 - h1); lp.y = pack2h(v2 - h2, v3 - h3);
                    *(uint2*)(hh + 2 * col) = hp;
                    *(uint2*)(hl + 2 * col) = lp;
                }
            }
            __syncthreads();
            // GEMM2: S += H @ W2a^T
#pragma unroll
            for (int sp = 0; sp < 2; sp++) {
                uint32_t ab = sbase + (sp ? HL_OFF : HH_OFF) + a2off;
                uint32_t bb = sbase + W2_OFF + b2off;
#pragma unroll
                for (int ks = 0; ks < 4; ks++) {
                    uint32_t a[2][4], b[4][4];
                    ldsm4(a[0], ab + ks * 32);
                    ldsm4(a[1], ab + ks * 32 + 16 * 144);
#pragma unroll
                    for (int p = 0; p < 4; p++)
                        ldsm4(b[p], bb + ks * 32 + p * 16 * 144);
#pragma unroll
                    for (int mt = 0; mt < 2; mt++)
#pragma unroll
                        for (int nt = 0; nt < 8; nt++)
                            mma16816(acc2[mt][nt], a[mt],
                                     b[nt >> 1][(nt & 1) * 2], b[nt >> 1][(nt & 1) * 2 + 1]);
                }
            }
        }
    }

    // =================== pass b: edge features, full MLP ===================
    {
        __syncthreads();   // pass-a done (B1Sf free, X region free)
        // stage X = ef hi/lo
        {
            int m = tid >> 1;
            int c0 = (tid & 1) * 64;
            int e = min(e0 + m, N_EDGES - 1);
            const float* pa = ef + (size_t)e * 128;
            char* xh = smem + XH_OFF + m * 272;
            char* xl = smem + XL_OFF + m * 272;
#pragma unroll 4
            for (int c4 = 0; c4 < 16; c4++) {
                int c = c0 + c4 * 4;
                float4 a = *(const float4*)(pa + c);
                float hx = __half2float(__float2half(a.x));
                float hy = __half2float(__float2half(a.y));
                float hz = __half2float(__float2half(a.z));
                float hw = __half2float(__float2half(a.w));
                uint2 hp, lp;
                hp.x = pack2h(a.x, a.y); hp.y = pack2h(a.z, a.w);
                lp.x = pack2h(a.x - hx, a.y - hy); lp.y = pack2h(a.z - hz, a.w - hw);
                *(uint2*)(xh + 2 * c) = hp;
                *(uint2*)(xl + 2 * c) = lp;
            }
            B1Sf[tid] = b1b[tid];
        }

        const __half* w1 = g_wq[1][0];
        const __half* w2 = g_wq[1][1];
        uint4 rw1[4], rw2[4];
#pragma unroll
        for (int q = 0; q < 4; q++) {
            rw1[q] = *(const uint4*)(w1 + (size_t)w1row[q] * 128 + w1c[q] * 8);
            rw2[q] = *(const uint4*)(w2 + (size_t)w2row[q] * 256 + 0 + w2c[q] * 8);
        }

#pragma unroll 1
        for (int chunk = 0; chunk < 4; chunk++) {
            const int hb = chunk * 64;
            __syncthreads();   // W/H free; X staged (first iter: staging above + this sync)
#pragma unroll
            for (int q = 0; q < 4; q++) {
                *(uint4*)(smem + W1_OFF + w1row[q] * 272 + w1c[q] * 16) = rw1[q];
                *(uint4*)(smem + W2_OFF + w2row[q] * 144 + w2c[q] * 16) = rw2[q];
            }
            if (chunk < 3) {
#pragma unroll
                for (int q = 0; q < 4; q++) {
                    rw1[q] = *(const uint4*)(w1 + (size_t)(hb + 64 + w1row[q]) * 128 + w1c[q] * 8);
                    rw2[q] = *(const uint4*)(w2 + (size_t)w2row[q] * 256 + hb + 64 + w2c[q] * 8);
                }
            }
            __syncthreads();

            // GEMM1: H = X @ W1b^T (2 splits)
            float acc1[2][4][4];
#pragma unroll
            for (int i = 0; i < 2; i++)
#pragma unroll
                for (int j = 0; j < 4; j++)
#pragma unroll
                    for (int c = 0; c < 4; c++) acc1[i][j][c] = 0.f;
#pragma unroll
            for (int sp = 0; sp < 2; sp++) {
                uint32_t ab = sbase + (sp ? XL_OFF : XH_OFF) + a1off;
                uint32_t bb = sbase + W1_OFF + b1off;
#pragma unroll
                for (int ks = 0; ks < 8; ks++) {
                    uint32_t a[2][4], b[2][4];
                    ldsm4(a[0], ab + ks * 32);
                    ldsm4(a[1], ab + ks * 32 + 16 * 272);
                    ldsm4(b[0], bb + ks * 32);
                    ldsm4(b[1], bb + ks * 32 + 16 * 272);
#pragma unroll
                    for (int mt = 0; mt < 2; mt++)
#pragma unroll
                        for (int nt = 0; nt < 4; nt++)
                            mma16816(acc1[mt][nt], a[mt],
                                     b[nt >> 1][(nt & 1) * 2], b[nt >> 1][(nt & 1) * 2 + 1]);
                }
            }
            // bias + relu + split -> H hi/lo
            {
                int g = lane >> 2, i2 = (lane & 3) * 2;
#pragma unroll
                for (int mt = 0; mt < 2; mt++)
#pragma unroll
                    for (int nt = 0; nt < 4; nt++) {
                        int row = 32 * wm + 16 * mt + g;
                        int col = 32 * wn + 8 * nt + i2;
                        float bb0 = B1Sf[hb + col], bb1 = B1Sf[hb + col + 1];
                        float v0 = fmaxf(acc1[mt][nt][0] + bb0, 0.f);
                        float v1 = fmaxf(acc1[mt][nt][1] + bb1, 0.f);
                        float v2 = fmaxf(acc1[mt][nt][2] + bb0, 0.f);
                        float v3 = fmaxf(acc1[mt][nt][3] + bb1, 0.f);
                        float h0 = __half2float(__float2half(v0));
                        float h1 = __half2float(__float2half(v1));
                        float h2 = __half2float(__float2half(v2));
                        float h3 = __half2float(__float2half(v3));
                        *(uint32_t*)(smem + HH_OFF + row * 144 + col * 2) = pack2h(v0, v1);
                        *(uint32_t*)(smem + HL_OFF + row * 144 + col * 2) = pack2h(v0 - h0, v1 - h1);
                        *(uint32_t*)(smem + HH_OFF + (row + 8) * 144 + col * 2) = pack2h(v2, v3);
                        *(uint32_t*)(smem + HL_OFF + (row + 8) * 144 + col * 2) = pack2h(v2 - h2, v3 - h3);
                    }
            }
            __syncthreads();

            // GEMM2: S += H @ W2b^T (2 splits)
#pragma unroll
            for (int sp = 0; sp < 2; sp++) {
                uint32_t ab = sbase + (sp ? HL_OFF : HH_OFF) + a2off;
                uint32_t bb = sbase + W2_OFF + b2off;
#pragma unroll
                for (int ks = 0; ks < 4; ks++) {
                    uint32_t a[2][4], b[4][4];
                    ldsm4(a[0], ab + ks * 32);
                    ldsm4(a[1], ab + ks * 32 + 16 * 144);
#pragma unroll
                    for (int p = 0; p < 4; p++)
                        ldsm4(b[p], bb + ks * 32 + p * 16 * 144);
#pragma unroll
                    for (int mt = 0; mt < 2; mt++)
#pragma unroll
                        for (int nt = 0; nt < 8; nt++)
                            mma16816(acc2[mt][nt], a[mt],
                                     b[nt >> 1][(nt & 1) * 2], b[nt >> 1][(nt & 1) * 2 + 1]);
                }
            }
        }
    }
    __syncthreads();   // all GEMMs done; W1/H areas free for S

    // ---- write S to smem (stride 132 floats = 528B, 16-aligned) ----
    {
        int g = lane >> 2, i2 = (lane & 3) * 2;
#pragma unroll
        for (int mt = 0; mt < 2; mt++)
#pragma unroll
            for (int nt = 0; nt < 8; nt++) {
                int row = 32 * wm + 16 * mt + g;
                int col = 64 * wn + 8 * nt + i2;
                Sf[row * 132 + col]       = acc2[mt][nt][0];
                Sf[row * 132 + col + 1]   = acc2[mt][nt][1];
                Sf[(row + 8) * 132 + col]     = acc2[mt][nt][2];
                Sf[(row + 8) * 132 + col + 1] = acc2[mt][nt][3];
            }
    }
    __syncthreads();

    // ---- per-row: +cvec, IN, dropout, relu ----
    if (tid < 128) {
        int m = tid;
        int e = min(e0 + m, N_EDGES - 1);
        float* Sr = Sf + m * 132;
        float sum = 0.f, sq = 0.f;
#pragma unroll 8
        for (int p = 0; p < 64; p++) {
            float2 v = *(float2*)(Sr + 2 * p);
            v.x += CVf[2 * p]; v.y += CVf[2 * p + 1];
            *(float2*)(Sr + 2 * p) = v;
            sum += v.x + v.y;
            sq  += v.x * v.x + v.y * v.y;
        }
        float mean = sum * 0.0078125f;
        float var  = sq * 0.0078125f - mean * mean;
        float rstd = rsqrtf(fmaxf(var, 0.f) + 1e-5f);
        unsigned mw[4];
#pragma unroll
        for (int i = 0; i < 4; i++) mw[i] = g_mask[4 * e + i];
#pragma unroll 8
        for (int p = 0; p < 64; p++) {
            int c0 = 2 * p, c1 = 2 * p + 1;
            float2 v = *(float2*)(Sr + c0);
            float x = (v.x - mean) * rstd;
            x = ((mw[c0 >> 5] >> (c0 & 31)) & 1u) ? x * (1.f / 0.9f) : 0.f;
            float y = (v.y - mean) * rstd;
            y = ((mw[c1 >> 5] >> (c1 & 31)) & 1u) ? y * (1.f / 0.9f) : 0.f;
            v.x = fmaxf(x, 0.f); v.y = fmaxf(y, 0.f);
            *(float2*)(Sr + c0) = v;
        }
    }
    __syncthreads();

    // ---- coalesced store with residual ----
#pragma unroll 4
    for (int q = 0; q < 16; q++) {
        int f = tid + q * 256;                 // 4096 float4
        int m = f >> 5, c4 = (f & 31) << 2;
        int e = e0 + m;
        if (e < N_EDGES) {
            float4 s = *(float4*)(Sf + m * 132 + c4);
            float4 ev = *(const float4*)(ef + (size_t)e * 128 + c4);
            s.x += ev.x; s.y += ev.y; s.z += ev.z; s.w += ev.w;
            *(float4*)(outp + (size_t)e * 128 + c4) = s;
        }
    }
}

extern "C" void kernel_launch(void* const* d_in, const int* in_sizes, int n_in,
                              void* d_out, int out_size) {
    const float* nf  = (const float*)d_in[0];
    const void*  ei  = d_in[1];
    const float* ef  = (const float*)d_in[2];
    const float* gf  = (const float*)d_in[3];
    const float* W1a = (const float*)d_in[4];
    const float* b1a = (const float*)d_in[5];
    const float* W2a = (const float*)d_in[6];
    const float* b2a = (const float*)d_in[7];
    const float* W1b = (const float*)d_in[8];
    const float* b1b = (const float*)d_in[9];
    const float* W2b = (const float*)d_in[10];
    const float* b2b = (const float*)d_in[11];
    const float* W1c = (const float*)d_in[12];
    const float* b1c = (const float*)d_in[13];
    const float* W2c = (const float*)d_in[14];
    const float* b2c = (const float*)d_in[15];
    float* out = (float*)d_out;

    ef_mask_kernel<<<(MASK_WORDS + 255) / 256, 256>>>();
    ef_detect_kernel<<<1, 32>>>((const unsigned*)ei);
    ef_hglob_kernel<<<1, 256>>>(gf, W1c, b1c, W2c, b2c, b2a, b2b);
    ef_prep_w<<<128, 256>>>(W1a, W2a, W1b, W2b);

    cudaFuncSetAttribute(ef_prep_p,
                         cudaFuncAttributeMaxDynamicSharedMemorySize, SMEM_BYTES_P);
    ef_prep_p<<<GRID_P, 256, SMEM_BYTES_P>>>(nf);

    cudaFuncSetAttribute(ef_main_kernel,
                         cudaFuncAttributeMaxDynamicSharedMemorySize, SMEM_BYTES);
    ef_main_kernel<<<GRID_MAIN, 256, SMEM_BYTES>>>(ei, ef, b1a, b1b, out);
}